// round 6
// baseline (speedup 1.0000x reference)
#include <cuda_runtime.h>
#include <math.h>
#include <stdint.h>

// FootAndBall ball-detection post-process.
//  in : [16, 2, 540, 960] fp32 logits
//  out: [16, 100, 5] fp32 (x1,y1,x2,y2,score), score desc (idx asc on ties).
//
//  K1 detect : d = x1-x0 (NMS on d == NMS on softmax prob, monotone).
//              Register-streaming 3x3 NMS; per-warp smem candidate queues;
//              fused per-block smem histogram of order-flipped d bits merged
//              into a global per-batch histogram.
//  K2 select : FUSED per-batch cut (log-parallel suffix scan of 4096-bin
//              hist) + survivor collect + exact (p desc, idx asc) rank +
//              box write + state reset for the next graph replay.
// __device__ globals are zero-initialized at load; K2 restores zeros.

#define BB   16
#define HH   540
#define WW   960
#define HWSZ (HH * WW)
#define KK   100

#define CH    36                  // rows per chunk; 540 = 15 * 36
#define NCH   15
#define WARPS 16                  // detect warps/block; covers 16*30=480 cols
#define QCAP  160                 // per-warp smem queue entries
#define SEGC  (CH * WW)           // worst-case candidates per (batch, chunk)
#define HB    4096                // histogram bins (top 12 flipped bits)
#define CAP   4096                // survivor capacity (expected ~110)

__device__ int    g_cnt [BB][NCH];
__device__ float2 g_cand[BB][NCH][SEGC];
__device__ int    g_hist[BB][HB];

// ---------------------------------------------------------------------------
// Exact softmax channel-1 prob from d = fl(x1-x0). Matches jax.nn.softmax:
// one exp arg is exactly 0 and fl(x0-x1) == -d exactly. (rel_err ~1e-12.)
// ---------------------------------------------------------------------------
__device__ __forceinline__ float prob_from_d(float d) {
#ifdef __FAST_MATH__
    double dd = (double)d;
    double p = (d >= 0.0f) ? (1.0 / (exp(-dd) + 1.0))
                           : (exp(dd) / (exp(dd) + 1.0));
    return (float)p;
#else
    if (d >= 0.0f) { float e0 = expf(-d); return 1.0f / (e0 + 1.0f); }
    else           { float e1 = expf(d);  return e1 / (1.0f + e1);  }
#endif
}

// Order-preserving bit flip: float compare == unsigned compare after flip.
__device__ __forceinline__ unsigned fflip(float f) {
    unsigned u = __float_as_uint(f);
    return u ^ (((unsigned)((int)u >> 31)) | 0x80000000u);
}

// ---------------------------------------------------------------------------
// K1: register-streaming NMS + queued emit + fused histogram.
// Grid (2, 15, 16), block 512 (16 warps x 30 output cols).
// ---------------------------------------------------------------------------
__device__ __forceinline__ void flush_queue(float2* __restrict__ sq, int& qcnt,
                                            int lane, int* __restrict__ ctr,
                                            float2* __restrict__ gseg) {
    if (qcnt == 0) return;                       // warp-uniform
    int base = 0;
    if (lane == 0) base = atomicAdd(ctr, qcnt);
    base = __shfl_sync(0xffffffffu, base, 0);
    for (int i = lane; i < qcnt; i += 32)        // coalesced bursts
        gseg[base + i] = sq[i];
    qcnt = 0;
}

__global__ __launch_bounds__(512) void detect_kernel(const float* __restrict__ in) {
    __shared__ float2 squeue[WARPS][QCAP];       // 20 KB
    __shared__ int    shist[HB];                 // 16 KB

    const int b     = blockIdx.z;
    const int chunk = blockIdx.y;
    const int w     = threadIdx.x >> 5;
    const int lane  = threadIdx.x & 31;
    const int tid   = threadIdx.x;
    const int col   = blockIdx.x * (WARPS * 30) + w * 30 + lane - 1;
    const bool colok = (col >= 0) && (col < WW);
    const int r0    = chunk * CH;

    #pragma unroll
    for (int i = tid; i < HB; i += 512) shist[i] = 0;
    __syncthreads();

    const float* __restrict__ p0 = in + (size_t)b * 2 * HWSZ;
    const float* __restrict__ p1 = p0 + HWSZ;

    int*    __restrict__ ctr  = &g_cnt[b][chunk];
    float2* __restrict__ gseg = g_cand[b][chunk];
    float2* __restrict__ sq   = squeue[w];
    int qcnt = 0;

    #define LOADROW(R) \
        ((colok && (unsigned)(R) < (unsigned)HH) \
            ? (__ldg(p1 + (R) * WW + col) - __ldg(p0 + (R) * WW + col)) \
            : -INFINITY)
    #define H3MAX(D, OUT) { \
        float _l = __shfl_up_sync(0xffffffffu, (D), 1); \
        float _r = __shfl_down_sync(0xffffffffu, (D), 1); \
        OUT = fmaxf(fmaxf(_l, (D)), _r); }

    float d_0, hm_m1, hm_0;
    { float d_m1 = LOADROW(r0 - 1); H3MAX(d_m1, hm_m1); }
    d_0 = LOADROW(r0);  H3MAX(d_0, hm_0);

    const bool lane_ok = (lane >= 1) && (lane <= 30) && (col < WW);
    const unsigned below = (1u << lane) - 1u;

    #pragma unroll 4
    for (int r = r0; r < r0 + CH; r++) {
        float d_p1 = LOADROW(r + 1);
        float hm_p1; H3MAX(d_p1, hm_p1);

        float m = fmaxf(fmaxf(hm_m1, hm_0), hm_p1);
        bool cand = lane_ok && (d_0 >= m);

        unsigned mask = __ballot_sync(0xffffffffu, cand);
        int nc = __popc(mask);
        if (qcnt + nc > QCAP) flush_queue(sq, qcnt, lane, ctr, gseg);
        if (cand) {
            int pos = qcnt + __popc(mask & below);
            sq[pos] = make_float2(d_0, __int_as_float(r * WW + col));
            atomicAdd(&shist[fflip(d_0) >> 20], 1);     // spread-address ATOMS
        }
        qcnt += nc;

        hm_m1 = hm_0; hm_0 = hm_p1; d_0 = d_p1;
    }
    flush_queue(sq, qcnt, lane, ctr, gseg);
    #undef LOADROW
    #undef H3MAX

    __syncthreads();
    // Merge nonzero bins into the global per-batch histogram.
    #pragma unroll
    for (int i = tid; i < HB; i += 512) {
        int v = shist[i];
        if (v) atomicAdd(&g_hist[b][i], v);
    }
}

// ---------------------------------------------------------------------------
// K2: fused cut + collect + rank + reset. Grid BB, block 512.
// ---------------------------------------------------------------------------
__global__ __launch_bounds__(512) void select_kernel(float* __restrict__ out) {
    __shared__ int      s_wtot[16];
    __shared__ unsigned s_cut;
    __shared__ int      s_count;
    __shared__ float    s_d[CAP];       // d, then overwritten in place by p
    __shared__ int      s_i[CAP];

    const int b = blockIdx.x;
    const int t = threadIdx.x;
    const int lane = t & 31;
    const int w    = t >> 5;
    const int* __restrict__ hb = g_hist[b];

    if (t == 0) s_count = 0;

    // ---- Phase A: cut via log-parallel suffix scan ------------------------
    // Thread t owns segment seg = 511 - t (descending bin value order), so an
    // ascending exclusive prefix over t == count of candidates ABOVE seg.
    const int seg = 511 - t;
    int val;
    {
        const int4* h4 = (const int4*)(hb + seg * 8);
        int4 a = h4[0], c = h4[1];
        val = a.x + a.y + a.z + a.w + c.x + c.y + c.z + c.w;
    }
    int incl = val;
    #pragma unroll
    for (int sh = 1; sh < 32; sh <<= 1) {
        int n = __shfl_up_sync(0xffffffffu, incl, sh);
        if (lane >= sh) incl += n;
    }
    if (lane == 31) s_wtot[w] = incl;
    __syncthreads();
    if (t < 16) {
        int v = s_wtot[t];
        int inc = v;
        #pragma unroll
        for (int sh = 1; sh < 16; sh <<= 1) {
            int n = __shfl_up_sync(0x0000ffffu, inc, sh);
            if (t >= sh) inc += n;
        }
        s_wtot[t] = inc - v;            // exclusive warp offset
    }
    __syncthreads();
    {
        int excl = incl - val + s_wtot[w];   // candidates strictly above seg
        if (excl < KK && excl + val >= KK) { // unique boundary thread
            int above = excl;
            int cut = seg * 8;
            for (int c = seg * 8 + 7; c >= seg * 8; c--) {
                int hv = hb[c];
                if (above + hv >= KK) { cut = c; break; }
                above += hv;
            }
            s_cut = ((unsigned)cut) << 20;
        }
    }
    __syncthreads();

    // ---- Phase B: collect survivors (>= cut). Expected ~110. --------------
    // No per-iteration warp sync: loads pipeline freely; smem atomic only on
    // the rare survivor hit.
    const unsigned cutbits = s_cut;
    for (int ch = 0; ch < NCH; ch++) {
        const int n = min(g_cnt[b][ch], SEGC);
        const float2* __restrict__ cd = g_cand[b][ch];
        for (int i = t; i < n; i += 512) {
            float2 v = cd[i];
            if (fflip(v.x) >= cutbits) {
                int pos = atomicAdd(&s_count, 1);
                if (pos < CAP) { s_d[pos] = v.x; s_i[pos] = __float_as_int(v.y); }
            }
        }
    }
    __syncthreads();

    const int C = min(s_count, CAP);

    // ---- Phase C: exact p (in place), then stable rank ---------------------
    for (int e = t; e < C; e += 512) s_d[e] = prob_from_d(s_d[e]);
    __syncthreads();

    for (int e = t; e < C; e += 512) {
        const float v  = s_d[e];
        const int   id = s_i[e];
        int rank = 0;
        for (int j = 0; j < C; j++) {
            float vj = s_d[j];
            rank += (vj > v) || (vj == v && s_i[j] < id);
        }
        if (rank < KK) {
            int ww = id % WW;
            int hh = id / WW;
            float xc = (float)ww * 4.0f + 1.5f;
            float yc = (float)hh * 4.0f + 1.5f;
            float* o = out + ((size_t)b * KK + rank) * 5;
            o[0] = xc - 10.0f;
            o[1] = yc - 10.0f;
            o[2] = xc + 10.0f;
            o[3] = yc + 10.0f;
            o[4] = v;
        }
    }

    // ---- Phase D: reset per-batch state for the next graph replay ---------
    #pragma unroll
    for (int i = t; i < HB; i += 512) g_hist[b][i] = 0;
    if (t < NCH) g_cnt[b][t] = 0;
}

// ---------------------------------------------------------------------------
extern "C" void kernel_launch(void* const* d_in, const int* in_sizes, int n_in,
                              void* d_out, int out_size) {
    const float* in = (const float*)d_in[0];
    float* out = (float*)d_out;

    dim3 dgrid(WW / (WARPS * 30), NCH, BB);      // (2, 15, 16)
    detect_kernel<<<dgrid, 512>>>(in);

    select_kernel<<<BB, 512>>>(out);
}

// round 7
// speedup vs baseline: 1.3638x; 1.3638x over previous
#include <cuda_runtime.h>
#include <math.h>
#include <stdint.h>

// FootAndBall ball-detection post-process.
//  in : [16, 2, 540, 960] fp32 logits
//  out: [16, 100, 5] fp32 (x1,y1,x2,y2,score), score desc (idx asc on ties).
//
//  K1 detect : d = x1-x0 (NMS on d == NMS on softmax prob, monotone).
//              Register-streaming 3x3 NMS; per-warp smem candidate queues;
//              per-block smem histogram -> BLOCK-LOCAL top-100 cut; only
//              candidates above the block cut are flushed to global (~110 per
//              block instead of ~1900). Global top-100 of a batch is always a
//              subset of the union of block-local top-100s. Queue overflow
//              falls back to unfiltered flush (superset -> still correct).
//  K2 select : per-batch smem histogram of the ~3.3k surviving candidates,
//              cut, collect, exact (p desc, idx asc) rank, box write, reset.
// __device__ globals are zero-initialized at load; K2 restores zeros.

#define BB   16
#define HH   540
#define WW   960
#define HWSZ (HH * WW)
#define KK   100

#define CH    36                  // rows per chunk; 540 = 15 * 36
#define NCH   15
#define WARPS 16                  // detect warps/block; covers 16*30=480 cols
#define QCAP  224                 // per-warp smem queue entries (exp ~120)
#define SEGC  (CH * WW)           // worst-case per (batch, chunk)
#define HB    4096                // histogram bins (top 12 flipped bits)
#define CAP   2048                // select survivor capacity (expected ~130)

__device__ int    g_cnt [BB][NCH];
__device__ float2 g_cand[BB][NCH][SEGC];

// ---------------------------------------------------------------------------
// Exact softmax channel-1 prob from d = fl(x1-x0). Matches jax.nn.softmax:
// one exp arg is exactly 0 and fl(x0-x1) == -d exactly. (rel_err ~1e-12.)
// ---------------------------------------------------------------------------
__device__ __forceinline__ float prob_from_d(float d) {
#ifdef __FAST_MATH__
    double dd = (double)d;
    double p = (d >= 0.0f) ? (1.0 / (exp(-dd) + 1.0))
                           : (exp(dd) / (exp(dd) + 1.0));
    return (float)p;
#else
    if (d >= 0.0f) { float e0 = expf(-d); return 1.0f / (e0 + 1.0f); }
    else           { float e1 = expf(d);  return e1 / (1.0f + e1);  }
#endif
}

// Order-preserving bit flip: float compare == unsigned compare after flip.
__device__ __forceinline__ unsigned fflip(float f) {
    unsigned u = __float_as_uint(f);
    return u ^ (((unsigned)((int)u >> 31)) | 0x80000000u);
}

// ---------------------------------------------------------------------------
// Log-parallel cut over a 4096-bin smem histogram with 512 threads.
// Result: *s_cut = smallest bin c with count(bin >= c) >= KK (0 if total<KK).
// Caller must zero *s_cut and __syncthreads() before, and sync after.
// ---------------------------------------------------------------------------
__device__ __forceinline__ void cut_scan(const int* __restrict__ hist,
                                         int* __restrict__ s_wtot,
                                         unsigned* __restrict__ s_cut,
                                         int t) {
    const int lane = t & 31;
    const int w    = t >> 5;
    const int seg  = 511 - t;               // descending bin order
    int val = 0;
    #pragma unroll
    for (int j = 0; j < 8; j++) val += hist[seg * 8 + j];

    int incl = val;
    #pragma unroll
    for (int sh = 1; sh < 32; sh <<= 1) {
        int n = __shfl_up_sync(0xffffffffu, incl, sh);
        if (lane >= sh) incl += n;
    }
    if (lane == 31) s_wtot[w] = incl;
    __syncthreads();
    if (t < 16) {
        int v = s_wtot[t];
        int inc = v;
        #pragma unroll
        for (int sh = 1; sh < 16; sh <<= 1) {
            int n = __shfl_up_sync(0x0000ffffu, inc, sh);
            if (t >= sh) inc += n;
        }
        s_wtot[t] = inc - v;                 // exclusive warp offset
    }
    __syncthreads();
    int excl = incl - val + s_wtot[w];       // count strictly above seg
    if (excl < KK && excl + val >= KK) {     // unique boundary thread
        int above = excl;
        int cut = seg * 8;
        #pragma unroll
        for (int c = seg * 8 + 7; c >= seg * 8; c--) {
            int hv = hist[c];
            if (above + hv >= KK) { cut = c; break; }
            above += hv;
        }
        *s_cut = ((unsigned)cut) << 20;
    }
}

// ---------------------------------------------------------------------------
// K1: register-streaming NMS + block-local top-100 filter.
// Grid (2, 15, 16), block 512 (16 warps x 30 output cols).
// ---------------------------------------------------------------------------
__device__ __forceinline__ void flush_unfiltered(float2* __restrict__ sq,
                                                 int& qcnt, int lane,
                                                 int* __restrict__ ctr,
                                                 float2* __restrict__ gseg) {
    if (qcnt == 0) return;                   // warp-uniform
    int base = 0;
    if (lane == 0) base = atomicAdd(ctr, qcnt);
    base = __shfl_sync(0xffffffffu, base, 0);
    for (int i = lane; i < qcnt; i += 32)
        gseg[base + i] = sq[i];
    qcnt = 0;
}

__global__ __launch_bounds__(512) void detect_kernel(const float* __restrict__ in) {
    __shared__ float2   squeue[WARPS][QCAP]; // 28 KB
    __shared__ int      shist[HB];           // 16 KB
    __shared__ int      s_wtot[16];
    __shared__ unsigned s_bcut;

    const int b     = blockIdx.z;
    const int chunk = blockIdx.y;
    const int w     = threadIdx.x >> 5;
    const int lane  = threadIdx.x & 31;
    const int tid   = threadIdx.x;
    const int col   = blockIdx.x * (WARPS * 30) + w * 30 + lane - 1;
    const bool colok = (col >= 0) && (col < WW);
    const int r0    = chunk * CH;

    #pragma unroll
    for (int i = tid; i < HB; i += 512) shist[i] = 0;
    if (tid == 0) s_bcut = 0u;
    __syncthreads();

    const float* __restrict__ p0 = in + (size_t)b * 2 * HWSZ;
    const float* __restrict__ p1 = p0 + HWSZ;

    int*    __restrict__ ctr  = &g_cnt[b][chunk];
    float2* __restrict__ gseg = g_cand[b][chunk];
    float2* __restrict__ sq   = squeue[w];
    int qcnt = 0;

    #define LOADROW(R) \
        ((colok && (unsigned)(R) < (unsigned)HH) \
            ? (__ldg(p1 + (R) * WW + col) - __ldg(p0 + (R) * WW + col)) \
            : -INFINITY)
    #define H3MAX(D, OUT) { \
        float _l = __shfl_up_sync(0xffffffffu, (D), 1); \
        float _r = __shfl_down_sync(0xffffffffu, (D), 1); \
        OUT = fmaxf(fmaxf(_l, (D)), _r); }

    float d_0, hm_m1, hm_0;
    { float d_m1 = LOADROW(r0 - 1); H3MAX(d_m1, hm_m1); }
    d_0 = LOADROW(r0);  H3MAX(d_0, hm_0);

    const bool lane_ok = (lane >= 1) && (lane <= 30) && (col < WW);
    const unsigned below = (1u << lane) - 1u;

    #pragma unroll 4
    for (int r = r0; r < r0 + CH; r++) {
        float d_p1 = LOADROW(r + 1);
        float hm_p1; H3MAX(d_p1, hm_p1);

        float m = fmaxf(fmaxf(hm_m1, hm_0), hm_p1);
        bool cand = lane_ok && (d_0 >= m);

        unsigned mask = __ballot_sync(0xffffffffu, cand);
        int nc = __popc(mask);
        if (qcnt + nc > QCAP)                     // rare; stays correct
            flush_unfiltered(sq, qcnt, lane, ctr, gseg);
        if (cand) {
            int pos = qcnt + __popc(mask & below);
            sq[pos] = make_float2(d_0, __int_as_float(r * WW + col));
            atomicAdd(&shist[fflip(d_0) >> 20], 1);
        }
        qcnt += nc;

        hm_m1 = hm_0; hm_0 = hm_p1; d_0 = d_p1;
    }
    #undef LOADROW
    #undef H3MAX

    // ---- Block-local top-100 cut ----
    __syncthreads();
    cut_scan(shist, s_wtot, &s_bcut, tid);
    __syncthreads();
    const unsigned bcut = s_bcut;

    // ---- Filtered, compacted flush of the warp queue ----
    int my = 0;
    for (int i = lane; i < qcnt; i += 32)
        my += (fflip(sq[i].x) >= bcut);
    #pragma unroll
    for (int sh = 16; sh >= 1; sh >>= 1)
        my += __shfl_down_sync(0xffffffffu, my, sh);
    int wbase = 0;
    if (lane == 0 && my > 0) wbase = atomicAdd(ctr, my);
    wbase = __shfl_sync(0xffffffffu, wbase, 0);

    int acc = 0;
    for (int i0 = 0; i0 < qcnt; i0 += 32) {
        int i = i0 + lane;
        float2 v = make_float2(0.f, 0.f);
        bool keep = false;
        if (i < qcnt) { v = sq[i]; keep = (fflip(v.x) >= bcut); }
        unsigned km = __ballot_sync(0xffffffffu, keep);
        if (keep) gseg[wbase + acc + __popc(km & below)] = v;
        acc += __popc(km);
    }
}

// ---------------------------------------------------------------------------
// K2: per-batch hist (of ~3.3k filtered candidates) + cut + collect + exact
// rank + box write + counter reset. Grid BB, block 512.
// ---------------------------------------------------------------------------
__global__ __launch_bounds__(512) void select_kernel(float* __restrict__ out) {
    __shared__ int      shist[HB];      // 16 KB
    __shared__ int      s_wtot[16];
    __shared__ unsigned s_cut;
    __shared__ int      s_count;
    __shared__ int      s_n[NCH];
    __shared__ float    s_d[CAP];       // d, overwritten in place by p
    __shared__ int      s_i[CAP];

    const int b = blockIdx.x;
    const int t = threadIdx.x;

    #pragma unroll
    for (int i = t; i < HB; i += 512) shist[i] = 0;
    if (t < NCH) s_n[t] = min(g_cnt[b][t], SEGC);
    if (t == 0) { s_cut = 0u; s_count = 0; }
    __syncthreads();

    if (t < NCH) g_cnt[b][t] = 0;       // reset for next graph replay

    // Pass 1: histogram of the filtered candidates (~3.3k total).
    for (int ch = 0; ch < NCH; ch++) {
        const int n = s_n[ch];
        const float2* __restrict__ cd = g_cand[b][ch];
        for (int i = t; i < n; i += 512)
            atomicAdd(&shist[fflip(cd[i].x) >> 20], 1);
    }
    __syncthreads();

    cut_scan(shist, s_wtot, &s_cut, t);
    __syncthreads();
    const unsigned cutbits = s_cut;

    // Pass 2: collect survivors (>= cut); candidate data now L1/L2-hot.
    for (int ch = 0; ch < NCH; ch++) {
        const int n = s_n[ch];
        const float2* __restrict__ cd = g_cand[b][ch];
        for (int i = t; i < n; i += 512) {
            float2 v = cd[i];
            if (fflip(v.x) >= cutbits) {
                int pos = atomicAdd(&s_count, 1);
                if (pos < CAP) { s_d[pos] = v.x; s_i[pos] = __float_as_int(v.y); }
            }
        }
    }
    __syncthreads();

    const int C = min(s_count, CAP);

    // Exact p in place, then exact stable rank: p desc, idx asc.
    for (int e = t; e < C; e += 512) s_d[e] = prob_from_d(s_d[e]);
    __syncthreads();

    for (int e = t; e < C; e += 512) {
        const float v  = s_d[e];
        const int   id = s_i[e];
        int rank = 0;
        for (int j = 0; j < C; j++) {
            float vj = s_d[j];
            rank += (vj > v) || (vj == v && s_i[j] < id);
        }
        if (rank < KK) {
            int ww = id % WW;
            int hh = id / WW;
            float xc = (float)ww * 4.0f + 1.5f;
            float yc = (float)hh * 4.0f + 1.5f;
            float* o = out + ((size_t)b * KK + rank) * 5;
            o[0] = xc - 10.0f;
            o[1] = yc - 10.0f;
            o[2] = xc + 10.0f;
            o[3] = yc + 10.0f;
            o[4] = v;
        }
    }
}

// ---------------------------------------------------------------------------
extern "C" void kernel_launch(void* const* d_in, const int* in_sizes, int n_in,
                              void* d_out, int out_size) {
    const float* in = (const float*)d_in[0];
    float* out = (float*)d_out;

    dim3 dgrid(WW / (WARPS * 30), NCH, BB);      // (2, 15, 16)
    detect_kernel<<<dgrid, 512>>>(in);

    select_kernel<<<BB, 512>>>(out);
}